// round 12
// baseline (speedup 1.0000x reference)
#include <cuda_runtime.h>
#include <cuda_bf16.h>
#include <cstdint>
#include <math.h>

// ---------------- problem constants ----------------
#define NB 8192
#define ND 256
#define TI 128
#define NSTRIP (NB / TI)                       // 64
#define NTILES ((NSTRIP * (NSTRIP + 1)) / 2)   // 2080 upper-triangle tiles
#define NCTAS 148
#define NTHREADS 256

#define SCALE 2.0609929155556619f   // log2(e)/0.7 -> accumulators in log2 domain
#define C_MAX SCALE
#define LN2F  0.6931471805599453f

// SMEM: A strip + 2 B buffers (PITCH=528 anti-conflict) + col-reduce scratch
#define PITCH 528
#define ASZ (TI * PITCH)            // 67584
#define SM_A  0
#define SM_B0 ASZ
#define BSZ   ASZ
#define SM_RED (SM_B0 + 2 * BSZ)    // 202752
#define SMEM_DYN (SM_RED + 2048)    // 204800

// ---------------- device scratch ----------------
__device__ __nv_bfloat16 g_a[NB * ND];   // bf16(e * SCALE)
__device__ __nv_bfloat16 g_b[NB * ND];   // bf16(e)
__device__ unsigned int  g_pk [NB];      // per-anchor pos-max, monotone-uint encoded
__device__ float         g_pns[NB];      // per-anchor sum exp2 over negatives
__device__ float         g_fs;           // final loss partial sum
__device__ int           g_fc;           // final valid count
__device__ int           g_fdone;        // finalize block completion counter

// ---------------- PTX helpers ----------------
__device__ __forceinline__ uint32_t smem_u32(const void* p) {
    uint32_t a;
    asm("{ .reg .u64 t; cvta.to.shared.u64 t, %1; cvt.u32.u64 %0, t; }" : "=r"(a) : "l"(p));
    return a;
}
__device__ __forceinline__ void cpa16(uint32_t dst, const void* src) {
    asm volatile("cp.async.cg.shared.global [%0], [%1], 16;" :: "r"(dst), "l"(src));
}
#define CP_COMMIT() asm volatile("cp.async.commit_group;" ::: "memory")
#define CP_WAIT1()  asm volatile("cp.async.wait_group 1;" ::: "memory")
#define CP_WAIT0()  asm volatile("cp.async.wait_group 0;" ::: "memory")

#define LDM_X4(r, addr)                                                          \
    asm volatile("ldmatrix.sync.aligned.m8n8.x4.shared.b16 {%0,%1,%2,%3}, [%4];" \
                 : "=r"((r)[0]), "=r"((r)[1]), "=r"((r)[2]), "=r"((r)[3])        \
                 : "r"(addr))
#define LDM_X4T(r, addr)                                                         \
    asm volatile("ldmatrix.sync.aligned.m8n8.x4.trans.shared.b16 {%0,%1,%2,%3}, [%4];" \
                 : "=r"((r)[0]), "=r"((r)[1]), "=r"((r)[2]), "=r"((r)[3])        \
                 : "r"(addr))
#define MMA_BF16(c, a, b0, b1)                                                   \
    asm volatile("mma.sync.aligned.m16n8k16.row.col.f32.bf16.bf16.f32 "          \
                 "{%0,%1,%2,%3}, {%4,%5,%6,%7}, {%8,%9}, {%0,%1,%2,%3};"         \
                 : "+f"((c)[0]), "+f"((c)[1]), "+f"((c)[2]), "+f"((c)[3])        \
                 : "r"((a)[0]), "r"((a)[1]), "r"((a)[2]), "r"((a)[3]),           \
                   "r"(b0), "r"(b1))

// monotone float->uint encoding (order-preserving; 0 = "none")
__device__ __forceinline__ unsigned int enc_f(float x) {
    unsigned int b = __float_as_uint(x);
    return (b & 0x80000000u) ? ~b : (b | 0x80000000u);
}
__device__ __forceinline__ float dec_f(unsigned int u) {
    unsigned int b = (u & 0x80000000u) ? (u & 0x7FFFFFFFu) : ~u;
    return __uint_as_float(b);
}

// ---------------- kernel 1: normalize (+ folded accumulator init) -----------
__global__ __launch_bounds__(NTHREADS) void normalize_kernel(const float* __restrict__ emb) {
    // fold init: first 32 blocks zero the accumulators (graph replays!)
    const int gi = blockIdx.x * NTHREADS + threadIdx.x;
    if (gi < NB) { g_pk[gi] = 0u; g_pns[gi] = 0.f; }
    if (gi == 0) { g_fs = 0.f; g_fc = 0; g_fdone = 0; }

    const int wid  = threadIdx.x >> 5;
    const int lane = threadIdx.x & 31;
    const int row  = blockIdx.x * 8 + wid;
    const float4* src = (const float4*)(emb + (size_t)row * ND);
    const float4 v0 = src[lane * 2];
    const float4 v1 = src[lane * 2 + 1];
    float s = v0.x * v0.x + v0.y * v0.y + v0.z * v0.z + v0.w * v0.w
            + v1.x * v1.x + v1.y * v1.y + v1.z * v1.z + v1.w * v1.w;
    #pragma unroll
    for (int o = 16; o > 0; o >>= 1) s += __shfl_xor_sync(0xFFFFFFFFu, s, o);
    const float inv = rsqrtf(s);
    float e[8] = { v0.x * inv, v0.y * inv, v0.z * inv, v0.w * inv,
                   v1.x * inv, v1.y * inv, v1.z * inv, v1.w * inv };
    uint4 pa, pb;
    uint32_t* paw = (uint32_t*)&pa;
    uint32_t* pbw = (uint32_t*)&pb;
    #pragma unroll
    for (int q = 0; q < 4; q++) {
        __nv_bfloat162 ha = __floats2bfloat162_rn(e[2 * q] * SCALE, e[2 * q + 1] * SCALE);
        __nv_bfloat162 hb = __floats2bfloat162_rn(e[2 * q], e[2 * q + 1]);
        paw[q] = *(uint32_t*)&ha;
        pbw[q] = *(uint32_t*)&hb;
    }
    ((uint4*)(g_a + (size_t)row * ND))[lane] = pa;
    ((uint4*)(g_b + (size_t)row * ND))[lane] = pb;
}

// ---------------- kernel 2: triangular persistent-tile HMMA -----------------
// 256 threads = 8 warps, 2x4 grid; warp tile 64x32. No cold tail code.
__global__ __launch_bounds__(NTHREADS) void loss_kernel(const int* __restrict__ cats) {
    extern __shared__ __align__(16) char sp[];
    const uint32_t sb = smem_u32(sp);
    float* sredp = (float*)(sp + SM_RED);          // [2][128]
    float* sredn = (float*)(sp + SM_RED + 1024);   // [2][128]

    const int t    = threadIdx.x;
    const int wid  = t >> 5;
    const int lane = t & 31;
    const int g    = lane >> 2;
    const int tg   = lane & 3;
    const int wrow = wid >> 2;     // 0..1
    const int wcol = wid & 3;      // 0..3

    // tile chunk [k0, k1)
    const int k0 = (int)(((long long)NTILES * blockIdx.x) / NCTAS);
    const int k1 = (int)(((long long)NTILES * (blockIdx.x + 1)) / NCTAS);

    // decode k0 -> (it, jt)
    int it = 0, acc = 0;
    while (acc + (NSTRIP - it) <= k0) { acc += NSTRIP - it; it++; }
    int jt = it + (k0 - acc);

    // fragment coordinate bookkeeping
    int rowidx[8], jcol[8];
    #pragma unroll
    for (int rs = 0; rs < 8; rs++) {
        rowidx[rs] = wrow * 64 + (rs >> 1) * 16 + (rs & 1) * 8 + g;
    }
    #pragma unroll
    for (int cs = 0; cs < 8; cs++) {
        jcol[cs] = wcol * 32 + (cs >> 1) * 8 + 2 * tg + (cs & 1);
    }

    const uint32_t a_lane = (uint32_t)(((lane & 7) + ((lane >> 3) & 1) * 8) * PITCH
                                       + (lane >> 4) * 16);
    const uint32_t b_lane = (uint32_t)(((lane & 7) + (lane >> 4) * 8) * PITCH
                                       + ((lane >> 3) & 1) * 16);

    // prologue: load A(it) + B(jt) into buf0
    {
        const __nv_bfloat16* Ag = g_a + (size_t)it * TI * ND;
        const __nv_bfloat16* Bg = g_b + (size_t)jt * TI * ND;
        #pragma unroll
        for (int m = 0; m < 16; m++) {
            const int idx = t + NTHREADS * m;
            const int r = idx >> 5, ch = idx & 31;
            cpa16(sb + SM_A + r * PITCH + ch * 16, Ag + r * ND + ch * 8);
        }
        #pragma unroll
        for (int m = 0; m < 16; m++) {
            const int idx = t + NTHREADS * m;
            const int r = idx >> 5, ch = idx & 31;
            cpa16(sb + SM_B0 + r * PITCH + ch * 16, Bg + r * ND + ch * 8);
        }
        CP_COMMIT();
    }

    int ci[8];
    #pragma unroll
    for (int rs = 0; rs < 8; rs++) {
        ci[rs] = cats[it * TI + rowidx[rs]];
    }

    float pmr[8], nsr[8];
    #pragma unroll
    for (int rs = 0; rs < 8; rs++) { pmr[rs] = -1e30f; nsr[rs] = 0.f; }

    int buf = 0;
    for (int k = k0; k < k1; k++) {
        const bool haveNext = (k + 1 < k1);
        int nit = it, njt = jt + 1;
        if (njt == NSTRIP) { nit = it + 1; njt = nit; }

        // prefetch next B tile (writes B[buf^1], not touched by prior epilogue)
        if (haveNext) {
            const __nv_bfloat16* Bg = g_b + (size_t)njt * TI * ND;
            const uint32_t dst = sb + SM_B0 + (uint32_t)(buf ^ 1) * BSZ;
            #pragma unroll
            for (int m = 0; m < 16; m++) {
                const int idx = t + NTHREADS * m;
                const int r = idx >> 5, ch = idx & 31;
                cpa16(dst + r * PITCH + ch * 16, Bg + r * ND + ch * 8);
            }
            CP_COMMIT();
            CP_WAIT1();     // A(current strip) + B(k) complete
        } else {
            CP_WAIT0();
        }
        __syncthreads();    // smem visibility of A + B[buf]; also fences prior-iter sred reads

        // ---- GEMM 128x128x256 ----
        float c[4][4][4];
        #pragma unroll
        for (int mt = 0; mt < 4; mt++) {
            #pragma unroll
            for (int nt = 0; nt < 4; nt++) {
                #pragma unroll
                for (int q = 0; q < 4; q++) { c[mt][nt][q] = 0.f; }
            }
        }

        const uint32_t aw = sb + SM_A + (uint32_t)(wrow * 64) * PITCH + a_lane;
        const uint32_t bw = sb + SM_B0 + (uint32_t)buf * BSZ
                            + (uint32_t)(wcol * 32) * PITCH + b_lane;
        #pragma unroll
        for (int ks = 0; ks < 16; ks++) {
            uint32_t a[4][4], bt[2][4];
            #pragma unroll
            for (int mt = 0; mt < 4; mt++) {
                LDM_X4(a[mt], aw + (uint32_t)(mt * 16) * PITCH + ks * 32);
            }
            #pragma unroll
            for (int np = 0; np < 2; np++) {
                LDM_X4T(bt[np], bw + (uint32_t)(np * 16) * PITCH + ks * 32);
            }
            #pragma unroll
            for (int mt = 0; mt < 4; mt++) {
                #pragma unroll
                for (int nt = 0; nt < 4; nt++) {
                    MMA_BF16(c[mt][nt], a[mt], bt[nt >> 1][(nt & 1) * 2],
                             bt[nt >> 1][(nt & 1) * 2 + 1]);
                }
            }
        }
        __syncthreads();   // all reads of A and B[buf] complete

        // strip changes next tile: A reload overlaps epilogue
        if (haveNext && nit != it) {
            const __nv_bfloat16* Ag = g_a + (size_t)nit * TI * ND;
            #pragma unroll
            for (int m = 0; m < 16; m++) {
                const int idx = t + NTHREADS * m;
                const int r = idx >> 5, ch = idx & 31;
                cpa16(sb + SM_A + r * PITCH + ch * 16, Ag + r * ND + ch * 8);
            }
            CP_COMMIT();
        }

        // ---- epilogue ----
        const int j0 = jt * TI;
        int cj[8];
        #pragma unroll
        for (int cs = 0; cs < 8; cs++) {
            cj[cs] = cats[j0 + jcol[cs]];
        }

        if (it == jt) {
            #pragma unroll
            for (int mt = 0; mt < 4; mt++) {
                #pragma unroll
                for (int h = 0; h < 2; h++) {
                    const int rs = mt * 2 + h;
                    #pragma unroll
                    for (int nt = 0; nt < 4; nt++) {
                        #pragma unroll
                        for (int l = 0; l < 2; l++) {
                            const int cs = nt * 2 + l;
                            const float v2 = c[mt][nt][h * 2 + l];
                            float ev;
                            asm("ex2.approx.f32 %0, %1;" : "=f"(ev) : "f"(v2));
                            const bool same = (ci[rs] == cj[cs]);
                            if (!same) { nsr[rs] += ev; }
                            else if (rowidx[rs] != jcol[cs]) { pmr[rs] = fmaxf(pmr[rs], v2); }
                        }
                    }
                }
            }
        } else {
            float pmc[8], nsc[8];
            #pragma unroll
            for (int cs = 0; cs < 8; cs++) { pmc[cs] = -1e30f; nsc[cs] = 0.f; }

            #pragma unroll
            for (int mt = 0; mt < 4; mt++) {
                #pragma unroll
                for (int h = 0; h < 2; h++) {
                    const int rs = mt * 2 + h;
                    #pragma unroll
                    for (int nt = 0; nt < 4; nt++) {
                        #pragma unroll
                        for (int l = 0; l < 2; l++) {
                            const int cs = nt * 2 + l;
                            const float v2 = c[mt][nt][h * 2 + l];
                            float ev;
                            asm("ex2.approx.f32 %0, %1;" : "=f"(ev) : "f"(v2));
                            const bool same = (ci[rs] == cj[cs]);
                            if (same) {
                                pmr[rs] = fmaxf(pmr[rs], v2);
                                pmc[cs] = fmaxf(pmc[cs], v2);
                            } else {
                                nsr[rs] += ev;
                                nsc[cs] += ev;
                            }
                        }
                    }
                }
            }

            // column reduce over g-lanes, then cross-wrow smem combine + 1 atomic pair/col
            #pragma unroll
            for (int cs = 0; cs < 8; cs++) {
                float p = pmc[cs], n = nsc[cs];
                #pragma unroll
                for (int o = 4; o < 32; o <<= 1) {
                    p = fmaxf(p, __shfl_xor_sync(0xFFFFFFFFu, p, o));
                    n += __shfl_xor_sync(0xFFFFFFFFu, n, o);
                }
                pmc[cs] = p; nsc[cs] = n;
            }
            if (lane < 4) {
                #pragma unroll
                for (int cs = 0; cs < 8; cs++) {
                    const int col = wcol * 32 + (cs >> 1) * 8 + 2 * lane + (cs & 1);
                    sredp[wrow * 128 + col] = pmc[cs];
                    sredn[wrow * 128 + col] = nsc[cs];
                }
            }
            __syncthreads();
            if (t < TI) {
                const float p = fmaxf(sredp[t], sredp[128 + t]);
                const float n = sredn[t] + sredn[128 + t];
                if (p > -1e29f) { atomicMax(&g_pk[j0 + t], enc_f(p)); }
                if (n != 0.f)   { atomicAdd(&g_pns[j0 + t], n); }
            }
        }

        // strip boundary: flush row stats, refresh ci
        if (haveNext && nit != it) {
            #pragma unroll
            for (int rs = 0; rs < 8; rs++) {
                const int ig = it * TI + rowidx[rs];
                if (pmr[rs] > -1e29f) { atomicMax(&g_pk[ig], enc_f(pmr[rs])); }
                if (nsr[rs] != 0.f)   { atomicAdd(&g_pns[ig], nsr[rs]); }
                pmr[rs] = -1e30f; nsr[rs] = 0.f;
                ci[rs] = cats[nit * TI + rowidx[rs]];
            }
        }
        // NOTE: no end-of-loop __syncthreads — next-iter top barrier fences
        // sred reuse, and prefetch writes only B[buf^1] (not read here).
        if (haveNext) { it = nit; jt = njt; }   // R7 OOB fix
        buf ^= 1;
    }

    // final row flush (it = strip of the last processed tile)
    #pragma unroll
    for (int rs = 0; rs < 8; rs++) {
        const int ig = it * TI + rowidx[rs];
        if (pmr[rs] > -1e29f) { atomicMax(&g_pk[ig], enc_f(pmr[rs])); }
        if (nsr[rs] != 0.f)   { atomicAdd(&g_pns[ig], nsr[rs]); }
    }
}

// ---------------- kernel 3: finalize (last block writes output) -------------
__global__ __launch_bounds__(512) void finalize_kernel(float* __restrict__ out) {
    const int i = blockIdx.x * 512 + threadIdx.x;   // 16 blocks x 512 = 8192
    float lsum = 0.f;
    int lcnt = 0;
    const unsigned int key = g_pk[i];
    const float s = g_pns[i];
    if (key != 0u && s > 0.f) {
        const float p = dec_f(key);
        if (p > -1e29f) {
            const float inv2C = exp2f(-C_MAX);
            lsum = LN2F * (log2f(exp2f(p - C_MAX) + s * inv2C) + C_MAX - p);
            lcnt = 1;
        }
    }
    #pragma unroll
    for (int o = 16; o > 0; o >>= 1) {
        lsum += __shfl_xor_sync(0xFFFFFFFFu, lsum, o);
        lcnt += __shfl_xor_sync(0xFFFFFFFFu, lcnt, o);
    }
    __shared__ float ss[16];
    __shared__ int sc[16];
    const int t = threadIdx.x;
    if ((t & 31) == 0) { ss[t >> 5] = lsum; sc[t >> 5] = lcnt; }
    __syncthreads();
    __shared__ int s_last;
    if (t == 0) {
        float S = 0.f; int C = 0;
        #pragma unroll
        for (int w = 0; w < 16; w++) { S += ss[w]; C += sc[w]; }
        atomicAdd(&g_fs, S);
        atomicAdd(&g_fc, C);
        __threadfence();
        s_last = (atomicAdd(&g_fdone, 1) == gridDim.x - 1) ? 1 : 0;
        if (s_last) {
            __threadfence();   // acquire: all blocks' g_fs/g_fc adds visible
            out[0] = g_fs / (float)(g_fc > 0 ? g_fc : 1);
        }
    }
}

extern "C" void kernel_launch(void* const* d_in, const int* in_sizes, int n_in,
                              void* d_out, int out_size) {
    (void)in_sizes; (void)n_in; (void)out_size;
    const float* emb  = (const float*)d_in[0];
    const int*   cats = (const int*)d_in[1];   // JAX x64-disabled -> int32
    float* out = (float*)d_out;

    normalize_kernel<<<NB / 8, NTHREADS>>>(emb);

    cudaFuncSetAttribute(loss_kernel, cudaFuncAttributeMaxDynamicSharedMemorySize, SMEM_DYN);
    loss_kernel<<<NCTAS, NTHREADS, SMEM_DYN>>>(cats);

    finalize_kernel<<<16, 512>>>(out);
}

// round 14
// speedup vs baseline: 1.0307x; 1.0307x over previous
#include <cuda_runtime.h>
#include <cuda_bf16.h>
#include <cstdint>
#include <math.h>

// ---------------- problem constants ----------------
#define NB 8192
#define ND 256
#define TI 128                     // A strip rows
#define TJ 64                      // B tile cols (rect tiles -> 2 CTAs/SM)
#define NSTRIP (NB / TI)           // 64
#define NJT (NB / TJ)              // 128
// upper-triangle rect tiles: per strip it, jt = 2*it .. 127 -> 128-2*it tiles
#define NTILES 4160                // sum_{it=0}^{63} (128 - 2*it)
#define NCTAS 296                  // 2 per SM
#define NTHREADS 256

#define SCALE 2.0609929155556619f  // log2(e)/0.7 -> v2 in log2 domain
#define C_MAX SCALE
#define LN2F  0.6931471805599453f

// SMEM: A strip + ONE B buffer (cross-CTA overlap replaces double buffering)
#define PITCH 528
#define ASZ (TI * PITCH)           // 67584
#define BSZ (TJ * PITCH)           // 33792
#define SM_A  0
#define SM_B  ASZ
#define SM_RED (SM_B + BSZ)        // 101376
#define SMEM_DYN (SM_RED + 1024)   // 102400  (x2 = 200 KB <= 228 KB/SM)

// ---------------- device scratch ----------------
__device__ __nv_bfloat16 g_a[NB * ND];   // bf16(e * SCALE)
__device__ __nv_bfloat16 g_b[NB * ND];   // bf16(e)
__device__ unsigned int  g_pk [NB];      // per-anchor pos-max, monotone-uint encoded
__device__ float         g_pns[NB];      // per-anchor sum exp2 over negatives
__device__ float         g_fs;           // final loss partial sum
__device__ int           g_fc;           // final valid count

// ---------------- PTX helpers ----------------
__device__ __forceinline__ uint32_t smem_u32(const void* p) {
    uint32_t a;
    asm("{ .reg .u64 t; cvta.to.shared.u64 t, %1; cvt.u32.u64 %0, t; }" : "=r"(a) : "l"(p));
    return a;
}
__device__ __forceinline__ void cpa16(uint32_t dst, const void* src) {
    asm volatile("cp.async.cg.shared.global [%0], [%1], 16;" :: "r"(dst), "l"(src));
}
#define CP_COMMIT() asm volatile("cp.async.commit_group;" ::: "memory")
#define CP_WAIT0()  asm volatile("cp.async.wait_group 0;" ::: "memory")

#define LDM_X4(r, addr)                                                          \
    asm volatile("ldmatrix.sync.aligned.m8n8.x4.shared.b16 {%0,%1,%2,%3}, [%4];" \
                 : "=r"((r)[0]), "=r"((r)[1]), "=r"((r)[2]), "=r"((r)[3])        \
                 : "r"(addr))
#define LDM_X4T(r, addr)                                                         \
    asm volatile("ldmatrix.sync.aligned.m8n8.x4.trans.shared.b16 {%0,%1,%2,%3}, [%4];" \
                 : "=r"((r)[0]), "=r"((r)[1]), "=r"((r)[2]), "=r"((r)[3])        \
                 : "r"(addr))
#define MMA_BF16(c, a, b0, b1)                                                   \
    asm volatile("mma.sync.aligned.m16n8k16.row.col.f32.bf16.bf16.f32 "          \
                 "{%0,%1,%2,%3}, {%4,%5,%6,%7}, {%8,%9}, {%0,%1,%2,%3};"         \
                 : "+f"((c)[0]), "+f"((c)[1]), "+f"((c)[2]), "+f"((c)[3])        \
                 : "r"((a)[0]), "r"((a)[1]), "r"((a)[2]), "r"((a)[3]),           \
                   "r"(b0), "r"(b1))

// monotone float->uint encoding (order-preserving; 0 = "none")
__device__ __forceinline__ unsigned int enc_f(float x) {
    unsigned int b = __float_as_uint(x);
    return (b & 0x80000000u) ? ~b : (b | 0x80000000u);
}
__device__ __forceinline__ float dec_f(unsigned int u) {
    unsigned int b = (u & 0x80000000u) ? (u & 0x7FFFFFFFu) : ~u;
    return __uint_as_float(b);
}

// ---------------- kernel 1: normalize (+ folded accumulator init) -----------
__global__ __launch_bounds__(NTHREADS) void normalize_kernel(const float* __restrict__ emb) {
    const int gi = blockIdx.x * NTHREADS + threadIdx.x;
    if (gi < NB) { g_pk[gi] = 0u; g_pns[gi] = 0.f; }
    if (gi == 0) { g_fs = 0.f; g_fc = 0; }

    const int wid  = threadIdx.x >> 5;
    const int lane = threadIdx.x & 31;
    const int row  = blockIdx.x * 8 + wid;
    const float4* src = (const float4*)(emb + (size_t)row * ND);
    const float4 v0 = src[lane * 2];
    const float4 v1 = src[lane * 2 + 1];
    float s = v0.x * v0.x + v0.y * v0.y + v0.z * v0.z + v0.w * v0.w
            + v1.x * v1.x + v1.y * v1.y + v1.z * v1.z + v1.w * v1.w;
    #pragma unroll
    for (int o = 16; o > 0; o >>= 1) s += __shfl_xor_sync(0xFFFFFFFFu, s, o);
    const float inv = rsqrtf(s);
    float e[8] = { v0.x * inv, v0.y * inv, v0.z * inv, v0.w * inv,
                   v1.x * inv, v1.y * inv, v1.z * inv, v1.w * inv };
    uint4 pa, pb;
    uint32_t* paw = (uint32_t*)&pa;
    uint32_t* pbw = (uint32_t*)&pb;
    #pragma unroll
    for (int q = 0; q < 4; q++) {
        __nv_bfloat162 ha = __floats2bfloat162_rn(e[2 * q] * SCALE, e[2 * q + 1] * SCALE);
        __nv_bfloat162 hb = __floats2bfloat162_rn(e[2 * q], e[2 * q + 1]);
        paw[q] = *(uint32_t*)&ha;
        pbw[q] = *(uint32_t*)&hb;
    }
    ((uint4*)(g_a + (size_t)row * ND))[lane] = pa;
    ((uint4*)(g_b + (size_t)row * ND))[lane] = pb;
}

// ---------------- kernel 2: triangular rect-tile HMMA, 2 CTAs/SM ------------
// 256 threads = 8 warps, 2x4 grid; warp tile 64x16.
__global__ __launch_bounds__(NTHREADS, 2) void loss_kernel(const int* __restrict__ cats) {
    extern __shared__ __align__(16) char sp[];
    const uint32_t sb = smem_u32(sp);
    float* sredp = (float*)(sp + SM_RED);         // [2][64]
    float* sredn = (float*)(sp + SM_RED + 512);   // [2][64]

    const int t    = threadIdx.x;
    const int wid  = t >> 5;
    const int lane = t & 31;
    const int g    = lane >> 2;
    const int tg   = lane & 3;
    const int wrow = wid >> 2;     // 0..1  (64 anchor rows each)
    const int wcol = wid & 3;      // 0..3  (16 j cols each)

    // tile chunk [k0, k1)
    const int k0 = (int)(((long long)NTILES * blockIdx.x) / NCTAS);
    const int k1 = (int)(((long long)NTILES * (blockIdx.x + 1)) / NCTAS);

    // decode k0 -> (it, jt): strip it has NJT - 2*it tiles, jt in [2*it, NJT)
    int it = 0, acc = 0;
    while (acc + (NJT - 2 * it) <= k0) { acc += NJT - 2 * it; it++; }
    int jt = 2 * it + (k0 - acc);

    // fragment coordinate bookkeeping: 8 row slots, 4 col slots
    int rowidx[8], jcol[4];
    #pragma unroll
    for (int rs = 0; rs < 8; rs++) {
        rowidx[rs] = wrow * 64 + (rs >> 1) * 16 + (rs & 1) * 8 + g;
    }
    #pragma unroll
    for (int cs = 0; cs < 4; cs++) {
        jcol[cs] = wcol * 16 + (cs >> 1) * 8 + 2 * tg + (cs & 1);
    }

    const uint32_t a_lane = (uint32_t)(((lane & 7) + ((lane >> 3) & 1) * 8) * PITCH
                                       + (lane >> 4) * 16);
    const uint32_t b_lane = (uint32_t)(((lane & 7) + (lane >> 4) * 8) * PITCH
                                       + ((lane >> 3) & 1) * 16);

    // prologue: load A(it) + B(jt)
    {
        const __nv_bfloat16* Ag = g_a + (size_t)it * TI * ND;
        const __nv_bfloat16* Bg = g_b + (size_t)jt * TJ * ND;
        #pragma unroll
        for (int m = 0; m < 16; m++) {
            const int idx = t + NTHREADS * m;     // 4096 chunks
            const int r = idx >> 5, ch = idx & 31;
            cpa16(sb + SM_A + r * PITCH + ch * 16, Ag + r * ND + ch * 8);
        }
        #pragma unroll
        for (int m = 0; m < 8; m++) {
            const int idx = t + NTHREADS * m;     // 2048 chunks
            const int r = idx >> 5, ch = idx & 31;
            cpa16(sb + SM_B + r * PITCH + ch * 16, Bg + r * ND + ch * 8);
        }
        CP_COMMIT();
    }

    int ci[8];
    #pragma unroll
    for (int rs = 0; rs < 8; rs++) {
        ci[rs] = cats[it * TI + rowidx[rs]];
    }

    float pmr[8], nsr[8];
    #pragma unroll
    for (int rs = 0; rs < 8; rs++) { pmr[rs] = -1e30f; nsr[rs] = 0.f; }

    for (int k = k0; k < k1; k++) {
        const bool haveNext = (k + 1 < k1);
        int nit = it, njt = jt + 1;
        if (njt == NJT) { nit = it + 1; njt = 2 * nit; }

        CP_WAIT0();
        __syncthreads();    // A + B(k) visible; also fences prior-iter sred reads

        // ---- GEMM 128x64x256 ----
        float c[4][2][4];
        #pragma unroll
        for (int mt = 0; mt < 4; mt++) {
            #pragma unroll
            for (int nt = 0; nt < 2; nt++) {
                #pragma unroll
                for (int q = 0; q < 4; q++) { c[mt][nt][q] = 0.f; }
            }
        }

        const uint32_t aw = sb + SM_A + (uint32_t)(wrow * 64) * PITCH + a_lane;
        const uint32_t bw = sb + SM_B + (uint32_t)(wcol * 16) * PITCH + b_lane;
        #pragma unroll
        for (int ks = 0; ks < 16; ks++) {
            uint32_t a[4][4], bt[4];
            #pragma unroll
            for (int mt = 0; mt < 4; mt++) {
                LDM_X4(a[mt], aw + (uint32_t)(mt * 16) * PITCH + ks * 32);
            }
            LDM_X4T(bt, bw + ks * 32);
            #pragma unroll
            for (int mt = 0; mt < 4; mt++) {
                #pragma unroll
                for (int nt = 0; nt < 2; nt++) {
                    MMA_BF16(c[mt][nt], a[mt], bt[nt * 2], bt[nt * 2 + 1]);
                }
            }
        }
        __syncthreads();   // all reads of A and B complete

        // prefetch next tile's B (+A on strip change) — overlaps epilogue,
        // and the co-resident CTA's GEMM covers the latency anyway.
        if (haveNext) {
            const __nv_bfloat16* Bg = g_b + (size_t)njt * TJ * ND;
            #pragma unroll
            for (int m = 0; m < 8; m++) {
                const int idx = t + NTHREADS * m;
                const int r = idx >> 5, ch = idx & 31;
                cpa16(sb + SM_B + r * PITCH + ch * 16, Bg + r * ND + ch * 8);
            }
            if (nit != it) {
                const __nv_bfloat16* Ag = g_a + (size_t)nit * TI * ND;
                #pragma unroll
                for (int m = 0; m < 16; m++) {
                    const int idx = t + NTHREADS * m;
                    const int r = idx >> 5, ch = idx & 31;
                    cpa16(sb + SM_A + r * PITCH + ch * 16, Ag + r * ND + ch * 8);
                }
            }
            CP_COMMIT();
        }

        // ---- epilogue ----
        const int j0 = jt * TJ;
        int cj[4];
        #pragma unroll
        for (int cs = 0; cs < 4; cs++) {
            cj[cs] = cats[j0 + jcol[cs]];
        }

        const bool isdiag = ((jt >> 1) == it);   // diag-class: row stats only

        if (isdiag) {
            const int i0 = it * TI;
            #pragma unroll
            for (int mt = 0; mt < 4; mt++) {
                #pragma unroll
                for (int h = 0; h < 2; h++) {
                    const int rs = mt * 2 + h;
                    #pragma unroll
                    for (int nt = 0; nt < 2; nt++) {
                        #pragma unroll
                        for (int l = 0; l < 2; l++) {
                            const int cs = nt * 2 + l;
                            const float v2 = c[mt][nt][h * 2 + l];
                            float ev;
                            asm("ex2.approx.f32 %0, %1;" : "=f"(ev) : "f"(v2));
                            const bool same = (ci[rs] == cj[cs]);
                            if (!same) { nsr[rs] += ev; }
                            else if (i0 + rowidx[rs] != j0 + jcol[cs]) {
                                pmr[rs] = fmaxf(pmr[rs], v2);
                            }
                        }
                    }
                }
            }
        } else {
            float pmc[4], nsc[4];
            #pragma unroll
            for (int cs = 0; cs < 4; cs++) { pmc[cs] = -1e30f; nsc[cs] = 0.f; }

            #pragma unroll
            for (int mt = 0; mt < 4; mt++) {
                #pragma unroll
                for (int h = 0; h < 2; h++) {
                    const int rs = mt * 2 + h;
                    #pragma unroll
                    for (int nt = 0; nt < 2; nt++) {
                        #pragma unroll
                        for (int l = 0; l < 2; l++) {
                            const int cs = nt * 2 + l;
                            const float v2 = c[mt][nt][h * 2 + l];
                            float ev;
                            asm("ex2.approx.f32 %0, %1;" : "=f"(ev) : "f"(v2));
                            const bool same = (ci[rs] == cj[cs]);
                            if (same) {
                                pmr[rs] = fmaxf(pmr[rs], v2);
                                pmc[cs] = fmaxf(pmc[cs], v2);
                            } else {
                                nsr[rs] += ev;
                                nsc[cs] += ev;
                            }
                        }
                    }
                }
            }

            // column reduce over g-lanes, then cross-wrow smem combine + 1 atomic pair/col
            #pragma unroll
            for (int cs = 0; cs < 4; cs++) {
                float p = pmc[cs], n = nsc[cs];
                #pragma unroll
                for (int o = 4; o < 32; o <<= 1) {
                    p = fmaxf(p, __shfl_xor_sync(0xFFFFFFFFu, p, o));
                    n += __shfl_xor_sync(0xFFFFFFFFu, n, o);
                }
                pmc[cs] = p; nsc[cs] = n;
            }
            if (lane < 4) {
                #pragma unroll
                for (int cs = 0; cs < 4; cs++) {
                    const int col = wcol * 16 + (cs >> 1) * 8 + 2 * lane + (cs & 1);
                    sredp[wrow * 64 + col] = pmc[cs];
                    sredn[wrow * 64 + col] = nsc[cs];
                }
            }
            __syncthreads();
            if (t < TJ) {
                const float p = fmaxf(sredp[t], sredp[64 + t]);
                const float n = sredn[t] + sredn[64 + t];
                if (p > -1e29f) { atomicMax(&g_pk[j0 + t], enc_f(p)); }
                if (n != 0.f)   { atomicAdd(&g_pns[j0 + t], n); }
            }
        }

        // strip boundary: flush row stats, refresh ci
        if (haveNext && nit != it) {
            #pragma unroll
            for (int rs = 0; rs < 8; rs++) {
                const int ig = it * TI + rowidx[rs];
                if (pmr[rs] > -1e29f) { atomicMax(&g_pk[ig], enc_f(pmr[rs])); }
                if (nsr[rs] != 0.f)   { atomicAdd(&g_pns[ig], nsr[rs]); }
                pmr[rs] = -1e30f; nsr[rs] = 0.f;
                ci[rs] = cats[nit * TI + rowidx[rs]];
            }
        }
        if (haveNext) { it = nit; jt = njt; }   // R7 OOB fix
    }

    // final row flush (it = strip of the last processed tile)
    #pragma unroll
    for (int rs = 0; rs < 8; rs++) {
        const int ig = it * TI + rowidx[rs];
        if (pmr[rs] > -1e29f) { atomicMax(&g_pk[ig], enc_f(pmr[rs])); }
        if (nsr[rs] != 0.f)   { atomicAdd(&g_pns[ig], nsr[rs]); }
    }
}

// ---------------- kernel 3a: per-anchor losses, distributed reduce ----------
__global__ __launch_bounds__(512) void finalize1_kernel() {
    const int i = blockIdx.x * 512 + threadIdx.x;   // 16 blocks x 512 = 8192
    float lsum = 0.f;
    int lcnt = 0;
    const unsigned int key = g_pk[i];
    const float s = g_pns[i];
    if (key != 0u && s > 0.f) {
        const float p = dec_f(key);
        if (p > -1e29f) {
            const float inv2C = exp2f(-C_MAX);
            lsum = LN2F * (log2f(exp2f(p - C_MAX) + s * inv2C) + C_MAX - p);
            lcnt = 1;
        }
    }
    #pragma unroll
    for (int o = 16; o > 0; o >>= 1) {
        lsum += __shfl_xor_sync(0xFFFFFFFFu, lsum, o);
        lcnt += __shfl_xor_sync(0xFFFFFFFFu, lcnt, o);
    }
    __shared__ float ss[16];
    __shared__ int sc[16];
    const int t = threadIdx.x;
    if ((t & 31) == 0) { ss[t >> 5] = lsum; sc[t >> 5] = lcnt; }
    __syncthreads();
    if (t == 0) {
        float S = 0.f; int C = 0;
        #pragma unroll
        for (int w = 0; w < 16; w++) { S += ss[w]; C += sc[w]; }
        atomicAdd(&g_fs, S);
        atomicAdd(&g_fc, C);
    }
}

// ---------------- kernel 3b: division ----------------
__global__ void finalize2_kernel(float* __restrict__ out) {
    out[0] = g_fs / (float)(g_fc > 0 ? g_fc : 1);
}

extern "C" void kernel_launch(void* const* d_in, const int* in_sizes, int n_in,
                              void* d_out, int out_size) {
    (void)in_sizes; (void)n_in; (void)out_size;
    const float* emb  = (const float*)d_in[0];
    const int*   cats = (const int*)d_in[1];   // JAX x64-disabled -> int32
    float* out = (float*)d_out;

    normalize_kernel<<<NB / 8, NTHREADS>>>(emb);

    cudaFuncSetAttribute(loss_kernel, cudaFuncAttributeMaxDynamicSharedMemorySize, SMEM_DYN);
    loss_kernel<<<NCTAS, NTHREADS, SMEM_DYN>>>(cats);

    finalize1_kernel<<<16, 512>>>();
    finalize2_kernel<<<1, 1>>>(out);
}